// round 8
// baseline (speedup 1.0000x reference)
#include <cuda_runtime.h>
#include <cuda_fp16.h>
#include <cstdint>

// ---------------------------------------------------------------------------
// GCN: out = SpMM(relu(SpMM(X@W1+b1)) @ W2 + b2)
// R8: R4 structure/kernels verbatim; sort chain reworked:
//     hist stores per-edge rank (atomic return) -> scatter is atomic-free;
//     3 scan kernels fused into 1 coalesced warp-shuffle scan.
// ---------------------------------------------------------------------------

#define MAX_NODES 100000
#define MAX_EDGES 1600000
#define FEAT 128

// Scratch
__device__ __align__(16) __half g_H [(size_t)MAX_NODES * FEAT];  // GEMM out (reused)
__device__ __align__(16) __half g_S1[(size_t)MAX_NODES * FEAT];  // relu(SpMM1)
__device__ int  g_cnt[MAX_NODES];
__device__ int  g_row_start[MAX_NODES + 1];
__device__ int  g_pos[MAX_EDGES];                  // within-row rank per edge
__device__ int2 g_edge[MAX_EDGES];                 // {col, float_as_int(val)}

// ---------------------------------------------------------------------------
// CSR build: zero -> hist_pos (atomic, stores rank) -> fused scan ->
//            scatter (NO atomics)
// ---------------------------------------------------------------------------
__global__ void zero_cnt_kernel(int* __restrict__ cnt, int n)
{
    int i = blockIdx.x * blockDim.x + threadIdx.x;
    if (i < n) cnt[i] = 0;
}

// p[e] = rank of edge e within its row (atomic ticket). cnt[r] ends as degree.
__global__ void hist_pos_kernel(const int* __restrict__ row, int nE,
                                int* __restrict__ cnt, int* __restrict__ pos)
{
    int i = blockIdx.x * blockDim.x + threadIdx.x;
    if (i < nE) pos[i] = atomicAdd(&cnt[row[i]], 1);
}

// Single-block exclusive scan, coalesced 1024-wide tiles, warp-shuffle scan.
__global__ __launch_bounds__(1024) void scan_fused_kernel(
    const int* __restrict__ cnt, int* __restrict__ row_start, int n)
{
    __shared__ int warp_off[32];
    __shared__ int tile_tot;
    const int tid  = threadIdx.x;
    const int lane = tid & 31;
    const int wid  = tid >> 5;

    int carry = 0;
    for (int base = 0; base < n; base += 1024) {
        int i = base + tid;
        int v = (i < n) ? cnt[i] : 0;
        int s = v;
#pragma unroll
        for (int off = 1; off < 32; off <<= 1) {
            int t = __shfl_up_sync(0xffffffffu, s, off);
            if (lane >= off) s += t;
        }
        if (lane == 31) warp_off[wid] = s;
        __syncthreads();
        if (wid == 0) {
            int wv = warp_off[lane];
            int ws = wv;
#pragma unroll
            for (int off = 1; off < 32; off <<= 1) {
                int t = __shfl_up_sync(0xffffffffu, ws, off);
                if (lane >= off) ws += t;
            }
            warp_off[lane] = ws - wv;
            if (lane == 31) tile_tot = ws;
        }
        __syncthreads();
        if (i < n) row_start[i] = s - v + warp_off[wid] + carry;
        carry += tile_tot;
        __syncthreads();
    }
    if (tid == 0) row_start[n] = carry;
}

// Atomic-free scatter: destination = row_start[row[e]] + pos[e].
__global__ void scatter_kernel(const int* __restrict__ row, const int* __restrict__ col,
                               const float* __restrict__ vals, const int* __restrict__ pos,
                               int nE, const int* __restrict__ row_start,
                               int2* __restrict__ edge)
{
    int i = blockIdx.x * blockDim.x + threadIdx.x;
    if (i < nE) {
        int p = row_start[row[i]] + pos[i];
        edge[p] = make_int2(col[i], __float_as_int(vals[i]));
    }
}

// ---------------------------------------------------------------------------
// HMMA GEMM (exact R4): C_h[M,128] = (A[M,K] @ W[K,128] + bias), fp32 accum.
// ---------------------------------------------------------------------------
__device__ __forceinline__ void mma16816(float* d, const uint32_t* a, const uint32_t* b)
{
    asm volatile(
        "mma.sync.aligned.m16n8k16.row.col.f32.f16.f16.f32 "
        "{%0,%1,%2,%3}, {%4,%5,%6,%7}, {%8,%9}, {%0,%1,%2,%3};\n"
        : "+f"(d[0]), "+f"(d[1]), "+f"(d[2]), "+f"(d[3])
        : "r"(a[0]), "r"(a[1]), "r"(a[2]), "r"(a[3]), "r"(b[0]), "r"(b[1]));
}

__device__ __forceinline__ void ldsm_x4(uint32_t* r, uint32_t addr)
{
    asm volatile("ldmatrix.sync.aligned.m8n8.x4.shared.b16 {%0,%1,%2,%3}, [%4];"
                 : "=r"(r[0]), "=r"(r[1]), "=r"(r[2]), "=r"(r[3]) : "r"(addr));
}

__device__ __forceinline__ void ldsm_x4_t(uint32_t* r, uint32_t addr)
{
    asm volatile("ldmatrix.sync.aligned.m8n8.x4.trans.shared.b16 {%0,%1,%2,%3}, [%4];"
                 : "=r"(r[0]), "=r"(r[1]), "=r"(r[2]), "=r"(r[3]) : "r"(addr));
}

#define AS_STRIDE 56
#define WS_STRIDE 136

template <int K, bool A_HALF>
__global__ __launch_bounds__(256) void gemm_hmma_kernel(
    const void* __restrict__ A_, const float* __restrict__ W,
    const float* __restrict__ bias, __half* __restrict__ C, int M)
{
    constexpr int BM = 128, BK = 32, N = 128;
    constexpr int T = K / BK;
    __shared__ __half As[BM * AS_STRIDE];
    __shared__ __half Ws[BK * WS_STRIDE];

    const int tid  = threadIdx.x;
    const int lane = tid & 31;
    const int wid  = tid >> 5;
    const int wm   = wid >> 1;
    const int wn   = wid & 1;
    const int m0   = blockIdx.x * BM;

    float acc[2][8][4];
#pragma unroll
    for (int i = 0; i < 2; i++)
#pragma unroll
        for (int j = 0; j < 8; j++)
#pragma unroll
            for (int q = 0; q < 4; q++) acc[i][j][q] = 0.f;

    const uint32_t sAs = (uint32_t)__cvta_generic_to_shared(As);
    const uint32_t sWs = (uint32_t)__cvta_generic_to_shared(Ws);

    for (int t = 0; t < T; t++) {
        const int k0 = t * BK;
        if (A_HALF) {
            const __half* A = (const __half*)A_;
#pragma unroll
            for (int i = 0; i < 2; i++) {
                int idx = tid + i * 256;
                int rr = idx >> 2, cc = (idx & 3) << 3;
                int gr = m0 + rr;
                uint4 v = make_uint4(0, 0, 0, 0);
                if (gr < M) v = *(const uint4*)(A + (size_t)gr * K + k0 + cc);
                *(uint4*)(&As[rr * AS_STRIDE + cc]) = v;
            }
        } else {
            const float* A = (const float*)A_;
#pragma unroll
            for (int i = 0; i < 4; i++) {
                int idx = tid + i * 256;
                int rr = idx >> 3, cc = (idx & 7) << 2;
                int gr = m0 + rr;
                float4 v = make_float4(0.f, 0.f, 0.f, 0.f);
                if (gr < M) v = *(const float4*)(A + (size_t)gr * K + k0 + cc);
                __half2* dst = (__half2*)(&As[rr * AS_STRIDE + cc]);
                dst[0] = __floats2half2_rn(v.x, v.y);
                dst[1] = __floats2half2_rn(v.z, v.w);
            }
        }
#pragma unroll
        for (int i = 0; i < 4; i++) {
            int idx = tid + i * 256;
            int rr = idx >> 5, cc = (idx & 31) << 2;
            float4 v = *(const float4*)(W + (size_t)(k0 + rr) * N + cc);
            __half2* dst = (__half2*)(&Ws[rr * WS_STRIDE + cc]);
            dst[0] = __floats2half2_rn(v.x, v.y);
            dst[1] = __floats2half2_rn(v.z, v.w);
        }
        __syncthreads();

#pragma unroll
        for (int ks = 0; ks < 2; ks++) {
            const int kk = ks * 16;
            uint32_t a[2][4], b[4][4];
#pragma unroll
            for (int mi = 0; mi < 2; mi++) {
                int r0 = wm * 32 + mi * 16;
                uint32_t addr = sAs + ((r0 + (lane & 15)) * AS_STRIDE
                                       + kk + ((lane >> 4) << 3)) * 2;
                ldsm_x4(a[mi], addr);
            }
#pragma unroll
            for (int p = 0; p < 4; p++) {
                int c0 = wn * 64 + p * 16;
                uint32_t addr = sWs + ((kk + (lane & 15)) * WS_STRIDE
                                       + c0 + ((lane >> 4) << 3)) * 2;
                ldsm_x4_t(b[p], addr);
            }
#pragma unroll
            for (int mi = 0; mi < 2; mi++)
#pragma unroll
                for (int p = 0; p < 4; p++) {
                    mma16816(acc[mi][2 * p],     a[mi], &b[p][0]);
                    mma16816(acc[mi][2 * p + 1], a[mi], &b[p][2]);
                }
        }
        __syncthreads();
    }

    const int rq = lane >> 2;
    const int cq = (lane & 3) << 1;
#pragma unroll
    for (int ni = 0; ni < 8; ni++) {
        int gc = wn * 64 + ni * 8 + cq;
        float2 bb = *(const float2*)(bias + gc);
#pragma unroll
        for (int mi = 0; mi < 2; mi++) {
            int r_base = m0 + wm * 32 + mi * 16 + rq;
            float* d = acc[mi][ni];
            if (r_base < M)
                *(__half2*)(C + (size_t)r_base * N + gc) =
                    __floats2half2_rn(d[0] + bb.x, d[1] + bb.y);
            if (r_base + 8 < M)
                *(__half2*)(C + (size_t)(r_base + 8) * N + gc) =
                    __floats2half2_rn(d[2] + bb.x, d[3] + bb.y);
        }
    }
}

// ---------------------------------------------------------------------------
// CSR SpMM (exact R4): warp per row, lane l owns features [4l..4l+3].
// ---------------------------------------------------------------------------
template <bool OUT_HALF_RELU>
__global__ __launch_bounds__(256) void spmm_csr_kernel(
    const int* __restrict__ row_start, const int2* __restrict__ edge,
    const __half* __restrict__ H, void* __restrict__ out_, int n)
{
    int r    = blockIdx.x * 8 + (threadIdx.x >> 5);
    int lane = threadIdx.x & 31;
    if (r >= n) return;

    int s = row_start[r];
    int e = row_start[r + 1];

    float4 acc = make_float4(0.f, 0.f, 0.f, 0.f);
    const int fo = lane << 2;

    auto fma_edge = [&](int2 ev) {
        float v = __int_as_float(ev.y);
        uint2 u = *(const uint2*)(H + (size_t)ev.x * FEAT + fo);
        float2 h01 = __half22float2(*(const __half2*)&u.x);
        float2 h23 = __half22float2(*(const __half2*)&u.y);
        acc.x += v * h01.x; acc.y += v * h01.y;
        acc.z += v * h23.x; acc.w += v * h23.y;
    };

    int i = s;
    for (; i + 4 <= e; i += 4) {
        int2 e0 = edge[i], e1 = edge[i + 1], e2 = edge[i + 2], e3 = edge[i + 3];
        fma_edge(e0); fma_edge(e1); fma_edge(e2); fma_edge(e3);
    }
    for (; i < e; i++) fma_edge(edge[i]);

    if (OUT_HALF_RELU) {
        __half* out = (__half*)out_;
        uint2 o;
        *(__half2*)&o.x = __floats2half2_rn(fmaxf(acc.x, 0.f), fmaxf(acc.y, 0.f));
        *(__half2*)&o.y = __floats2half2_rn(fmaxf(acc.z, 0.f), fmaxf(acc.w, 0.f));
        *(uint2*)(out + (size_t)r * FEAT + fo) = o;
    } else {
        float* out = (float*)out_;
        *(float4*)(out + (size_t)r * FEAT + fo) = acc;
    }
}

// ---------------------------------------------------------------------------
extern "C" void kernel_launch(void* const* d_in, const int* in_sizes, int n_in,
                              void* d_out, int out_size)
{
    const float* X    = (const float*)d_in[0];
    const float* W1   = (const float*)d_in[1];
    const float* b1   = (const float*)d_in[2];
    const float* W2   = (const float*)d_in[3];
    const float* b2   = (const float*)d_in[4];
    const float* vals = (const float*)d_in[5];
    const int*   row  = (const int*)d_in[6];
    const int*   col  = (const int*)d_in[7];

    const int M  = in_sizes[0] / 256;   // 100000
    const int nE = in_sizes[5];         // 1600000

    __half *H, *S1;
    int *cnt, *row_start, *pos;
    int2 *edge;
    cudaGetSymbolAddress((void**)&H,         g_H);
    cudaGetSymbolAddress((void**)&S1,        g_S1);
    cudaGetSymbolAddress((void**)&cnt,       g_cnt);
    cudaGetSymbolAddress((void**)&row_start, g_row_start);
    cudaGetSymbolAddress((void**)&pos,       g_pos);
    cudaGetSymbolAddress((void**)&edge,      g_edge);
    float* out = (float*)d_out;

    static cudaStream_t s_side = nullptr;
    static cudaEvent_t  ev_fork = nullptr, ev_join = nullptr;
    if (s_side == nullptr) {
        cudaStreamCreateWithFlags(&s_side, cudaStreamNonBlocking);
        cudaEventCreateWithFlags(&ev_fork, cudaEventDisableTiming);
        cudaEventCreateWithFlags(&ev_join, cudaEventDisableTiming);
    }

    // ---- Fork: CSR build on side stream, concurrent with GEMM1 ----
    cudaEventRecord(ev_fork, 0);
    cudaStreamWaitEvent(s_side, ev_fork, 0);

    zero_cnt_kernel<<<(M + 511) / 512, 512, 0, s_side>>>(cnt, M);
    hist_pos_kernel<<<(nE + 511) / 512, 512, 0, s_side>>>(row, nE, cnt, pos);
    scan_fused_kernel<<<1, 1024, 0, s_side>>>(cnt, row_start, M);
    scatter_kernel<<<(nE + 511) / 512, 512, 0, s_side>>>(
        row, col, vals, pos, nE, row_start, edge);
    cudaEventRecord(ev_join, s_side);

    // ---- Main: GEMM1 (concurrent with CSR build) ----
    const int gemm_blocks = (M + 127) / 128;
    gemm_hmma_kernel<256, false><<<gemm_blocks, 256>>>(X, W1, b1, H, M);

    cudaStreamWaitEvent(0, ev_join, 0);
    spmm_csr_kernel<true><<<(M + 7) / 8, 256>>>(row_start, edge, H, S1, M);
    gemm_hmma_kernel<128, true><<<gemm_blocks, 256>>>(S1, W2, b2, H, M);
    spmm_csr_kernel<false><<<(M + 7) / 8, 256>>>(row_start, edge, H, out, M);
}

// round 9
// speedup vs baseline: 1.3434x; 1.3434x over previous
#include <cuda_runtime.h>
#include <cuda_fp16.h>
#include <cstdint>

// ---------------------------------------------------------------------------
// GCN: out = SpMM(relu(SpMM(X@W1+b1)) @ W2 + b2)
// R9: R4 structure/kernels verbatim + R8's hist_pos & atomic-free scatter,
//     with the R4-proven MULTI-BLOCK 3-kernel scan (the single-block fused
//     scan serialized ~70us of memory latency on one SM — reverted).
// ---------------------------------------------------------------------------

#define MAX_NODES 100000
#define MAX_EDGES 1600000
#define FEAT 128
#define SCAN_B 512
#define SCAN_NB ((MAX_NODES + SCAN_B - 1) / SCAN_B)

// Scratch
__device__ __align__(16) __half g_H [(size_t)MAX_NODES * FEAT];  // GEMM out (reused)
__device__ __align__(16) __half g_S1[(size_t)MAX_NODES * FEAT];  // relu(SpMM1)
__device__ int  g_cnt[MAX_NODES];
__device__ int  g_row_start[MAX_NODES + 1];
__device__ int  g_partials[SCAN_NB];
__device__ int  g_pos[MAX_EDGES];                  // within-row rank per edge
__device__ int2 g_edge[MAX_EDGES];                 // {col, float_as_int(val)}

// ---------------------------------------------------------------------------
// CSR build: zero -> hist_pos -> scan1/scan2/scan3 (multi-block) ->
//            scatter (atomic-free)
// ---------------------------------------------------------------------------
__global__ void zero_cnt_kernel(int* __restrict__ cnt, int n)
{
    int i = blockIdx.x * blockDim.x + threadIdx.x;
    if (i < n) cnt[i] = 0;
}

// pos[e] = rank of edge e within its row (atomic ticket). cnt[r] ends as degree.
__global__ void hist_pos_kernel(const int* __restrict__ row, int nE,
                                int* __restrict__ cnt, int* __restrict__ pos)
{
    int i = blockIdx.x * blockDim.x + threadIdx.x;
    if (i < nE) pos[i] = atomicAdd(&cnt[row[i]], 1);
}

__global__ void scan1_kernel(const int* __restrict__ cnt, int* __restrict__ partials, int n)
{
    __shared__ int sh[SCAN_B];
    int i = blockIdx.x * SCAN_B + threadIdx.x;
    sh[threadIdx.x] = (i < n) ? cnt[i] : 0;
    __syncthreads();
#pragma unroll
    for (int off = SCAN_B / 2; off > 0; off >>= 1) {
        if (threadIdx.x < off) sh[threadIdx.x] += sh[threadIdx.x + off];
        __syncthreads();
    }
    if (threadIdx.x == 0) partials[blockIdx.x] = sh[0];
}

__global__ void scan2_kernel(int* __restrict__ partials, int nb,
                             int* __restrict__ row_start, int n)
{
    __shared__ int sh[256];
    int tid = threadIdx.x;
    int v = (tid < nb) ? partials[tid] : 0;
    sh[tid] = v;
    __syncthreads();
#pragma unroll
    for (int off = 1; off < 256; off <<= 1) {
        int t = (tid >= off) ? sh[tid - off] : 0;
        __syncthreads();
        sh[tid] += t;
        __syncthreads();
    }
    if (tid < nb) partials[tid] = sh[tid] - v;        // exclusive block offsets
    if (tid == 255) row_start[n] = sh[255];           // grand total
}

__global__ void scan3_kernel(const int* __restrict__ cnt, const int* __restrict__ partials,
                             int* __restrict__ row_start, int n)
{
    __shared__ int sh[SCAN_B];
    int tid = threadIdx.x;
    int i = blockIdx.x * SCAN_B + tid;
    int v = (i < n) ? cnt[i] : 0;
    sh[tid] = v;
    __syncthreads();
#pragma unroll
    for (int off = 1; off < SCAN_B; off <<= 1) {
        int t = (tid >= off) ? sh[tid - off] : 0;
        __syncthreads();
        sh[tid] += t;
        __syncthreads();
    }
    if (i < n) row_start[i] = sh[tid] - v + partials[blockIdx.x];
}

// Atomic-free scatter: destination = row_start[row[e]] + pos[e].
__global__ void scatter_kernel(const int* __restrict__ row, const int* __restrict__ col,
                               const float* __restrict__ vals, const int* __restrict__ pos,
                               int nE, const int* __restrict__ row_start,
                               int2* __restrict__ edge)
{
    int i = blockIdx.x * blockDim.x + threadIdx.x;
    if (i < nE) {
        int p = row_start[row[i]] + pos[i];
        edge[p] = make_int2(col[i], __float_as_int(vals[i]));
    }
}

// ---------------------------------------------------------------------------
// HMMA GEMM (exact R4): C_h[M,128] = (A[M,K] @ W[K,128] + bias), fp32 accum.
// ---------------------------------------------------------------------------
__device__ __forceinline__ void mma16816(float* d, const uint32_t* a, const uint32_t* b)
{
    asm volatile(
        "mma.sync.aligned.m16n8k16.row.col.f32.f16.f16.f32 "
        "{%0,%1,%2,%3}, {%4,%5,%6,%7}, {%8,%9}, {%0,%1,%2,%3};\n"
        : "+f"(d[0]), "+f"(d[1]), "+f"(d[2]), "+f"(d[3])
        : "r"(a[0]), "r"(a[1]), "r"(a[2]), "r"(a[3]), "r"(b[0]), "r"(b[1]));
}

__device__ __forceinline__ void ldsm_x4(uint32_t* r, uint32_t addr)
{
    asm volatile("ldmatrix.sync.aligned.m8n8.x4.shared.b16 {%0,%1,%2,%3}, [%4];"
                 : "=r"(r[0]), "=r"(r[1]), "=r"(r[2]), "=r"(r[3]) : "r"(addr));
}

__device__ __forceinline__ void ldsm_x4_t(uint32_t* r, uint32_t addr)
{
    asm volatile("ldmatrix.sync.aligned.m8n8.x4.trans.shared.b16 {%0,%1,%2,%3}, [%4];"
                 : "=r"(r[0]), "=r"(r[1]), "=r"(r[2]), "=r"(r[3]) : "r"(addr));
}

#define AS_STRIDE 56
#define WS_STRIDE 136

template <int K, bool A_HALF>
__global__ __launch_bounds__(256) void gemm_hmma_kernel(
    const void* __restrict__ A_, const float* __restrict__ W,
    const float* __restrict__ bias, __half* __restrict__ C, int M)
{
    constexpr int BM = 128, BK = 32, N = 128;
    constexpr int T = K / BK;
    __shared__ __half As[BM * AS_STRIDE];
    __shared__ __half Ws[BK * WS_STRIDE];

    const int tid  = threadIdx.x;
    const int lane = tid & 31;
    const int wid  = tid >> 5;
    const int wm   = wid >> 1;
    const int wn   = wid & 1;
    const int m0   = blockIdx.x * BM;

    float acc[2][8][4];
#pragma unroll
    for (int i = 0; i < 2; i++)
#pragma unroll
        for (int j = 0; j < 8; j++)
#pragma unroll
            for (int q = 0; q < 4; q++) acc[i][j][q] = 0.f;

    const uint32_t sAs = (uint32_t)__cvta_generic_to_shared(As);
    const uint32_t sWs = (uint32_t)__cvta_generic_to_shared(Ws);

    for (int t = 0; t < T; t++) {
        const int k0 = t * BK;
        if (A_HALF) {
            const __half* A = (const __half*)A_;
#pragma unroll
            for (int i = 0; i < 2; i++) {
                int idx = tid + i * 256;
                int rr = idx >> 2, cc = (idx & 3) << 3;
                int gr = m0 + rr;
                uint4 v = make_uint4(0, 0, 0, 0);
                if (gr < M) v = *(const uint4*)(A + (size_t)gr * K + k0 + cc);
                *(uint4*)(&As[rr * AS_STRIDE + cc]) = v;
            }
        } else {
            const float* A = (const float*)A_;
#pragma unroll
            for (int i = 0; i < 4; i++) {
                int idx = tid + i * 256;
                int rr = idx >> 3, cc = (idx & 7) << 2;
                int gr = m0 + rr;
                float4 v = make_float4(0.f, 0.f, 0.f, 0.f);
                if (gr < M) v = *(const float4*)(A + (size_t)gr * K + k0 + cc);
                __half2* dst = (__half2*)(&As[rr * AS_STRIDE + cc]);
                dst[0] = __floats2half2_rn(v.x, v.y);
                dst[1] = __floats2half2_rn(v.z, v.w);
            }
        }
#pragma unroll
        for (int i = 0; i < 4; i++) {
            int idx = tid + i * 256;
            int rr = idx >> 5, cc = (idx & 31) << 2;
            float4 v = *(const float4*)(W + (size_t)(k0 + rr) * N + cc);
            __half2* dst = (__half2*)(&Ws[rr * WS_STRIDE + cc]);
            dst[0] = __floats2half2_rn(v.x, v.y);
            dst[1] = __floats2half2_rn(v.z, v.w);
        }
        __syncthreads();

#pragma unroll
        for (int ks = 0; ks < 2; ks++) {
            const int kk = ks * 16;
            uint32_t a[2][4], b[4][4];
#pragma unroll
            for (int mi = 0; mi < 2; mi++) {
                int r0 = wm * 32 + mi * 16;
                uint32_t addr = sAs + ((r0 + (lane & 15)) * AS_STRIDE
                                       + kk + ((lane >> 4) << 3)) * 2;
                ldsm_x4(a[mi], addr);
            }
#pragma unroll
            for (int p = 0; p < 4; p++) {
                int c0 = wn * 64 + p * 16;
                uint32_t addr = sWs + ((kk + (lane & 15)) * WS_STRIDE
                                       + c0 + ((lane >> 4) << 3)) * 2;
                ldsm_x4_t(b[p], addr);
            }
#pragma unroll
            for (int mi = 0; mi < 2; mi++)
#pragma unroll
                for (int p = 0; p < 4; p++) {
                    mma16816(acc[mi][2 * p],     a[mi], &b[p][0]);
                    mma16816(acc[mi][2 * p + 1], a[mi], &b[p][2]);
                }
        }
        __syncthreads();
    }

    const int rq = lane >> 2;
    const int cq = (lane & 3) << 1;
#pragma unroll
    for (int ni = 0; ni < 8; ni++) {
        int gc = wn * 64 + ni * 8 + cq;
        float2 bb = *(const float2*)(bias + gc);
#pragma unroll
        for (int mi = 0; mi < 2; mi++) {
            int r_base = m0 + wm * 32 + mi * 16 + rq;
            float* d = acc[mi][ni];
            if (r_base < M)
                *(__half2*)(C + (size_t)r_base * N + gc) =
                    __floats2half2_rn(d[0] + bb.x, d[1] + bb.y);
            if (r_base + 8 < M)
                *(__half2*)(C + (size_t)(r_base + 8) * N + gc) =
                    __floats2half2_rn(d[2] + bb.x, d[3] + bb.y);
        }
    }
}

// ---------------------------------------------------------------------------
// CSR SpMM (exact R4): warp per row, lane l owns features [4l..4l+3].
// ---------------------------------------------------------------------------
template <bool OUT_HALF_RELU>
__global__ __launch_bounds__(256) void spmm_csr_kernel(
    const int* __restrict__ row_start, const int2* __restrict__ edge,
    const __half* __restrict__ H, void* __restrict__ out_, int n)
{
    int r    = blockIdx.x * 8 + (threadIdx.x >> 5);
    int lane = threadIdx.x & 31;
    if (r >= n) return;

    int s = row_start[r];
    int e = row_start[r + 1];

    float4 acc = make_float4(0.f, 0.f, 0.f, 0.f);
    const int fo = lane << 2;

    auto fma_edge = [&](int2 ev) {
        float v = __int_as_float(ev.y);
        uint2 u = *(const uint2*)(H + (size_t)ev.x * FEAT + fo);
        float2 h01 = __half22float2(*(const __half2*)&u.x);
        float2 h23 = __half22float2(*(const __half2*)&u.y);
        acc.x += v * h01.x; acc.y += v * h01.y;
        acc.z += v * h23.x; acc.w += v * h23.y;
    };

    int i = s;
    for (; i + 4 <= e; i += 4) {
        int2 e0 = edge[i], e1 = edge[i + 1], e2 = edge[i + 2], e3 = edge[i + 3];
        fma_edge(e0); fma_edge(e1); fma_edge(e2); fma_edge(e3);
    }
    for (; i < e; i++) fma_edge(edge[i]);

    if (OUT_HALF_RELU) {
        __half* out = (__half*)out_;
        uint2 o;
        *(__half2*)&o.x = __floats2half2_rn(fmaxf(acc.x, 0.f), fmaxf(acc.y, 0.f));
        *(__half2*)&o.y = __floats2half2_rn(fmaxf(acc.z, 0.f), fmaxf(acc.w, 0.f));
        *(uint2*)(out + (size_t)r * FEAT + fo) = o;
    } else {
        float* out = (float*)out_;
        *(float4*)(out + (size_t)r * FEAT + fo) = acc;
    }
}

// ---------------------------------------------------------------------------
extern "C" void kernel_launch(void* const* d_in, const int* in_sizes, int n_in,
                              void* d_out, int out_size)
{
    const float* X    = (const float*)d_in[0];
    const float* W1   = (const float*)d_in[1];
    const float* b1   = (const float*)d_in[2];
    const float* W2   = (const float*)d_in[3];
    const float* b2   = (const float*)d_in[4];
    const float* vals = (const float*)d_in[5];
    const int*   row  = (const int*)d_in[6];
    const int*   col  = (const int*)d_in[7];

    const int M  = in_sizes[0] / 256;   // 100000
    const int nE = in_sizes[5];         // 1600000

    __half *H, *S1;
    int *cnt, *row_start, *partials, *pos;
    int2 *edge;
    cudaGetSymbolAddress((void**)&H,         g_H);
    cudaGetSymbolAddress((void**)&S1,        g_S1);
    cudaGetSymbolAddress((void**)&cnt,       g_cnt);
    cudaGetSymbolAddress((void**)&row_start, g_row_start);
    cudaGetSymbolAddress((void**)&partials,  g_partials);
    cudaGetSymbolAddress((void**)&pos,       g_pos);
    cudaGetSymbolAddress((void**)&edge,      g_edge);
    float* out = (float*)d_out;

    static cudaStream_t s_side = nullptr;
    static cudaEvent_t  ev_fork = nullptr, ev_join = nullptr;
    if (s_side == nullptr) {
        cudaStreamCreateWithFlags(&s_side, cudaStreamNonBlocking);
        cudaEventCreateWithFlags(&ev_fork, cudaEventDisableTiming);
        cudaEventCreateWithFlags(&ev_join, cudaEventDisableTiming);
    }

    const int nb = (M + SCAN_B - 1) / SCAN_B;   // 196

    // ---- Fork: CSR build on side stream, concurrent with GEMM1 ----
    cudaEventRecord(ev_fork, 0);
    cudaStreamWaitEvent(s_side, ev_fork, 0);

    zero_cnt_kernel<<<(M + 511) / 512, 512, 0, s_side>>>(cnt, M);
    hist_pos_kernel<<<(nE + 511) / 512, 512, 0, s_side>>>(row, nE, cnt, pos);
    scan1_kernel<<<nb, SCAN_B, 0, s_side>>>(cnt, partials, M);
    scan2_kernel<<<1, 256, 0, s_side>>>(partials, nb, row_start, M);
    scan3_kernel<<<nb, SCAN_B, 0, s_side>>>(cnt, partials, row_start, M);
    scatter_kernel<<<(nE + 511) / 512, 512, 0, s_side>>>(
        row, col, vals, pos, nE, row_start, edge);
    cudaEventRecord(ev_join, s_side);

    // ---- Main: GEMM1 (concurrent with CSR build) ----
    const int gemm_blocks = (M + 127) / 128;
    gemm_hmma_kernel<256, false><<<gemm_blocks, 256>>>(X, W1, b1, H, M);

    cudaStreamWaitEvent(0, ev_join, 0);
    spmm_csr_kernel<true><<<(M + 7) / 8, 256>>>(row_start, edge, H, S1, M);
    gemm_hmma_kernel<128, true><<<gemm_blocks, 256>>>(S1, W2, b2, H, M);
    spmm_csr_kernel<false><<<(M + 7) / 8, 256>>>(row_start, edge, H, out, M);
}

// round 10
// speedup vs baseline: 1.3782x; 1.0259x over previous
#include <cuda_runtime.h>
#include <cuda_fp16.h>
#include <cstdint>

// ---------------------------------------------------------------------------
// GCN: out = SpMM(relu(SpMM(X@W1+b1)) @ W2 + b2)
// R10: exact R4 pipeline (proven 199.5us) with three deltas:
//   1) zero_cnt launch removed (scan3 restores cnt=0 after reading it)
//   2) enqueue order puts GEMM1 at launch index 3 (ncu captures #3)
//   3) SpMM2 final fp32 store uses __stcs (evict-first; output is never
//      re-read, keeps the H2 gather table resident in L2)
// ---------------------------------------------------------------------------

#define MAX_NODES 100000
#define MAX_EDGES 1600000
#define FEAT 128
#define SCAN_B 512
#define SCAN_NB ((MAX_NODES + SCAN_B - 1) / SCAN_B)

// Scratch (device globals are zero-initialized: cnt starts at 0 on call 1,
// and scan3 restores cnt=0 every call thereafter).
__device__ __align__(16) __half g_H [(size_t)MAX_NODES * FEAT];  // GEMM out (reused)
__device__ __align__(16) __half g_S1[(size_t)MAX_NODES * FEAT];  // relu(SpMM1)
__device__ int  g_cnt[MAX_NODES];
__device__ int  g_row_start[MAX_NODES + 1];
__device__ int  g_row_next[MAX_NODES];
__device__ int  g_partials[SCAN_NB];
__device__ int2 g_edge[MAX_EDGES];                 // {col, float_as_int(val)}

// ---------------------------------------------------------------------------
// CSR build: hist (RED) -> scan1/scan2/scan3 (multi-block; scan3 re-zeros cnt)
//            -> scatter (atomic ticket)
// ---------------------------------------------------------------------------
__global__ void hist_kernel(const int* __restrict__ row, int nE, int* __restrict__ cnt)
{
    int i = blockIdx.x * blockDim.x + threadIdx.x;
    if (i < nE) atomicAdd(&cnt[row[i]], 1);        // returnless -> RED
}

__global__ void scan1_kernel(const int* __restrict__ cnt, int* __restrict__ partials, int n)
{
    __shared__ int sh[SCAN_B];
    int i = blockIdx.x * SCAN_B + threadIdx.x;
    sh[threadIdx.x] = (i < n) ? cnt[i] : 0;
    __syncthreads();
#pragma unroll
    for (int off = SCAN_B / 2; off > 0; off >>= 1) {
        if (threadIdx.x < off) sh[threadIdx.x] += sh[threadIdx.x + off];
        __syncthreads();
    }
    if (threadIdx.x == 0) partials[blockIdx.x] = sh[0];
}

__global__ void scan2_kernel(int* __restrict__ partials, int nb,
                             int* __restrict__ row_start, int n)
{
    __shared__ int sh[256];
    int tid = threadIdx.x;
    int v = (tid < nb) ? partials[tid] : 0;
    sh[tid] = v;
    __syncthreads();
#pragma unroll
    for (int off = 1; off < 256; off <<= 1) {
        int t = (tid >= off) ? sh[tid - off] : 0;
        __syncthreads();
        sh[tid] += t;
        __syncthreads();
    }
    if (tid < nb) partials[tid] = sh[tid] - v;        // exclusive block offsets
    if (tid == 255) row_start[n] = sh[255];           // grand total
}

// scan3 additionally restores cnt[i]=0 for the next call (invariant).
__global__ void scan3_kernel(int* __restrict__ cnt, const int* __restrict__ partials,
                             int* __restrict__ row_start, int* __restrict__ row_next, int n)
{
    __shared__ int sh[SCAN_B];
    int tid = threadIdx.x;
    int i = blockIdx.x * SCAN_B + tid;
    int v = (i < n) ? cnt[i] : 0;
    sh[tid] = v;
    __syncthreads();
#pragma unroll
    for (int off = 1; off < SCAN_B; off <<= 1) {
        int t = (tid >= off) ? sh[tid - off] : 0;
        __syncthreads();
        sh[tid] += t;
        __syncthreads();
    }
    if (i < n) {
        int excl = sh[tid] - v + partials[blockIdx.x];
        row_start[i] = excl;
        row_next[i]  = excl;
        cnt[i]       = 0;      // restore for next call
    }
}

__global__ void scatter_kernel(const int* __restrict__ row, const int* __restrict__ col,
                               const float* __restrict__ vals, int nE,
                               int* __restrict__ row_next, int2* __restrict__ edge)
{
    int i = blockIdx.x * blockDim.x + threadIdx.x;
    if (i < nE) {
        int r = row[i];
        int p = atomicAdd(&row_next[r], 1);
        edge[p] = make_int2(col[i], __float_as_int(vals[i]));
    }
}

// ---------------------------------------------------------------------------
// HMMA GEMM (exact R4): C_h[M,128] = (A[M,K] @ W[K,128] + bias), fp32 accum.
// ---------------------------------------------------------------------------
__device__ __forceinline__ void mma16816(float* d, const uint32_t* a, const uint32_t* b)
{
    asm volatile(
        "mma.sync.aligned.m16n8k16.row.col.f32.f16.f16.f32 "
        "{%0,%1,%2,%3}, {%4,%5,%6,%7}, {%8,%9}, {%0,%1,%2,%3};\n"
        : "+f"(d[0]), "+f"(d[1]), "+f"(d[2]), "+f"(d[3])
        : "r"(a[0]), "r"(a[1]), "r"(a[2]), "r"(a[3]), "r"(b[0]), "r"(b[1]));
}

__device__ __forceinline__ void ldsm_x4(uint32_t* r, uint32_t addr)
{
    asm volatile("ldmatrix.sync.aligned.m8n8.x4.shared.b16 {%0,%1,%2,%3}, [%4];"
                 : "=r"(r[0]), "=r"(r[1]), "=r"(r[2]), "=r"(r[3]) : "r"(addr));
}

__device__ __forceinline__ void ldsm_x4_t(uint32_t* r, uint32_t addr)
{
    asm volatile("ldmatrix.sync.aligned.m8n8.x4.trans.shared.b16 {%0,%1,%2,%3}, [%4];"
                 : "=r"(r[0]), "=r"(r[1]), "=r"(r[2]), "=r"(r[3]) : "r"(addr));
}

#define AS_STRIDE 56
#define WS_STRIDE 136

template <int K, bool A_HALF>
__global__ __launch_bounds__(256) void gemm_hmma_kernel(
    const void* __restrict__ A_, const float* __restrict__ W,
    const float* __restrict__ bias, __half* __restrict__ C, int M)
{
    constexpr int BM = 128, BK = 32, N = 128;
    constexpr int T = K / BK;
    __shared__ __half As[BM * AS_STRIDE];
    __shared__ __half Ws[BK * WS_STRIDE];

    const int tid  = threadIdx.x;
    const int lane = tid & 31;
    const int wid  = tid >> 5;
    const int wm   = wid >> 1;
    const int wn   = wid & 1;
    const int m0   = blockIdx.x * BM;

    float acc[2][8][4];
#pragma unroll
    for (int i = 0; i < 2; i++)
#pragma unroll
        for (int j = 0; j < 8; j++)
#pragma unroll
            for (int q = 0; q < 4; q++) acc[i][j][q] = 0.f;

    const uint32_t sAs = (uint32_t)__cvta_generic_to_shared(As);
    const uint32_t sWs = (uint32_t)__cvta_generic_to_shared(Ws);

    for (int t = 0; t < T; t++) {
        const int k0 = t * BK;
        if (A_HALF) {
            const __half* A = (const __half*)A_;
#pragma unroll
            for (int i = 0; i < 2; i++) {
                int idx = tid + i * 256;
                int rr = idx >> 2, cc = (idx & 3) << 3;
                int gr = m0 + rr;
                uint4 v = make_uint4(0, 0, 0, 0);
                if (gr < M) v = *(const uint4*)(A + (size_t)gr * K + k0 + cc);
                *(uint4*)(&As[rr * AS_STRIDE + cc]) = v;
            }
        } else {
            const float* A = (const float*)A_;
#pragma unroll
            for (int i = 0; i < 4; i++) {
                int idx = tid + i * 256;
                int rr = idx >> 3, cc = (idx & 7) << 2;
                int gr = m0 + rr;
                float4 v = make_float4(0.f, 0.f, 0.f, 0.f);
                if (gr < M) v = *(const float4*)(A + (size_t)gr * K + k0 + cc);
                __half2* dst = (__half2*)(&As[rr * AS_STRIDE + cc]);
                dst[0] = __floats2half2_rn(v.x, v.y);
                dst[1] = __floats2half2_rn(v.z, v.w);
            }
        }
#pragma unroll
        for (int i = 0; i < 4; i++) {
            int idx = tid + i * 256;
            int rr = idx >> 5, cc = (idx & 31) << 2;
            float4 v = *(const float4*)(W + (size_t)(k0 + rr) * N + cc);
            __half2* dst = (__half2*)(&Ws[rr * WS_STRIDE + cc]);
            dst[0] = __floats2half2_rn(v.x, v.y);
            dst[1] = __floats2half2_rn(v.z, v.w);
        }
        __syncthreads();

#pragma unroll
        for (int ks = 0; ks < 2; ks++) {
            const int kk = ks * 16;
            uint32_t a[2][4], b[4][4];
#pragma unroll
            for (int mi = 0; mi < 2; mi++) {
                int r0 = wm * 32 + mi * 16;
                uint32_t addr = sAs + ((r0 + (lane & 15)) * AS_STRIDE
                                       + kk + ((lane >> 4) << 3)) * 2;
                ldsm_x4(a[mi], addr);
            }
#pragma unroll
            for (int p = 0; p < 4; p++) {
                int c0 = wn * 64 + p * 16;
                uint32_t addr = sWs + ((kk + (lane & 15)) * WS_STRIDE
                                       + c0 + ((lane >> 4) << 3)) * 2;
                ldsm_x4_t(b[p], addr);
            }
#pragma unroll
            for (int mi = 0; mi < 2; mi++)
#pragma unroll
                for (int p = 0; p < 4; p++) {
                    mma16816(acc[mi][2 * p],     a[mi], &b[p][0]);
                    mma16816(acc[mi][2 * p + 1], a[mi], &b[p][2]);
                }
        }
        __syncthreads();
    }

    const int rq = lane >> 2;
    const int cq = (lane & 3) << 1;
#pragma unroll
    for (int ni = 0; ni < 8; ni++) {
        int gc = wn * 64 + ni * 8 + cq;
        float2 bb = *(const float2*)(bias + gc);
#pragma unroll
        for (int mi = 0; mi < 2; mi++) {
            int r_base = m0 + wm * 32 + mi * 16 + rq;
            float* d = acc[mi][ni];
            if (r_base < M)
                *(__half2*)(C + (size_t)r_base * N + gc) =
                    __floats2half2_rn(d[0] + bb.x, d[1] + bb.y);
            if (r_base + 8 < M)
                *(__half2*)(C + (size_t)(r_base + 8) * N + gc) =
                    __floats2half2_rn(d[2] + bb.x, d[3] + bb.y);
        }
    }
}

// ---------------------------------------------------------------------------
// CSR SpMM (exact R4 body): warp per row, lane l owns features [4l..4l+3].
// OUT_HALF_RELU: fp16+relu store (re-read by GEMM2 -> default caching).
// else: final fp32 out, never re-read -> __stcs evict-first store.
// ---------------------------------------------------------------------------
template <bool OUT_HALF_RELU>
__global__ __launch_bounds__(256) void spmm_csr_kernel(
    const int* __restrict__ row_start, const int2* __restrict__ edge,
    const __half* __restrict__ H, void* __restrict__ out_, int n)
{
    int r    = blockIdx.x * 8 + (threadIdx.x >> 5);
    int lane = threadIdx.x & 31;
    if (r >= n) return;

    int s = row_start[r];
    int e = row_start[r + 1];

    float4 acc = make_float4(0.f, 0.f, 0.f, 0.f);
    const int fo = lane << 2;

    auto fma_edge = [&](int2 ev) {
        float v = __int_as_float(ev.y);
        uint2 u = *(const uint2*)(H + (size_t)ev.x * FEAT + fo);
        float2 h01 = __half22float2(*(const __half2*)&u.x);
        float2 h23 = __half22float2(*(const __half2*)&u.y);
        acc.x += v * h01.x; acc.y += v * h01.y;
        acc.z += v * h23.x; acc.w += v * h23.y;
    };

    int i = s;
    for (; i + 4 <= e; i += 4) {
        int2 e0 = edge[i], e1 = edge[i + 1], e2 = edge[i + 2], e3 = edge[i + 3];
        fma_edge(e0); fma_edge(e1); fma_edge(e2); fma_edge(e3);
    }
    for (; i < e; i++) fma_edge(edge[i]);

    if (OUT_HALF_RELU) {
        __half* out = (__half*)out_;
        uint2 o;
        *(__half2*)&o.x = __floats2half2_rn(fmaxf(acc.x, 0.f), fmaxf(acc.y, 0.f));
        *(__half2*)&o.y = __floats2half2_rn(fmaxf(acc.z, 0.f), fmaxf(acc.w, 0.f));
        *(uint2*)(out + (size_t)r * FEAT + fo) = o;
    } else {
        float* out = (float*)out_;
        __stcs((float4*)(out + (size_t)r * FEAT + fo), acc);   // evict-first
    }
}

// ---------------------------------------------------------------------------
extern "C" void kernel_launch(void* const* d_in, const int* in_sizes, int n_in,
                              void* d_out, int out_size)
{
    const float* X    = (const float*)d_in[0];
    const float* W1   = (const float*)d_in[1];
    const float* b1   = (const float*)d_in[2];
    const float* W2   = (const float*)d_in[3];
    const float* b2   = (const float*)d_in[4];
    const float* vals = (const float*)d_in[5];
    const int*   row  = (const int*)d_in[6];
    const int*   col  = (const int*)d_in[7];

    const int M  = in_sizes[0] / 256;   // 100000
    const int nE = in_sizes[5];         // 1600000

    __half *H, *S1;
    int *cnt, *row_start, *row_next, *partials;
    int2 *edge;
    cudaGetSymbolAddress((void**)&H,         g_H);
    cudaGetSymbolAddress((void**)&S1,        g_S1);
    cudaGetSymbolAddress((void**)&cnt,       g_cnt);
    cudaGetSymbolAddress((void**)&row_start, g_row_start);
    cudaGetSymbolAddress((void**)&row_next,  g_row_next);
    cudaGetSymbolAddress((void**)&partials,  g_partials);
    cudaGetSymbolAddress((void**)&edge,      g_edge);
    float* out = (float*)d_out;

    static cudaStream_t s_side = nullptr;
    static cudaEvent_t  ev_fork = nullptr, ev_join = nullptr;
    if (s_side == nullptr) {
        cudaStreamCreateWithFlags(&s_side, cudaStreamNonBlocking);
        cudaEventCreateWithFlags(&ev_fork, cudaEventDisableTiming);
        cudaEventCreateWithFlags(&ev_join, cudaEventDisableTiming);
    }

    const int nb = (M + SCAN_B - 1) / SCAN_B;   // 196
    const int gemm_blocks = (M + 127) / 128;

    // ---- Fork: CSR build on side stream, concurrent with GEMM1 ----
    // Enqueue order chosen so GEMM1 is kernel launch #3 (ncu captures #3).
    cudaEventRecord(ev_fork, 0);
    cudaStreamWaitEvent(s_side, ev_fork, 0);

    hist_kernel<<<(nE + 511) / 512, 512, 0, s_side>>>(row, nE, cnt);          // #0
    scan1_kernel<<<nb, SCAN_B, 0, s_side>>>(cnt, partials, M);                // #1
    scan2_kernel<<<1, 256, 0, s_side>>>(partials, nb, row_start, M);          // #2
    gemm_hmma_kernel<256, false><<<gemm_blocks, 256>>>(X, W1, b1, H, M);      // #3 (main)
    scan3_kernel<<<nb, SCAN_B, 0, s_side>>>(cnt, partials, row_start,
                                            row_next, M);                     // #4
    scatter_kernel<<<(nE + 511) / 512, 512, 0, s_side>>>(row, col, vals, nE,
                                                         row_next, edge);     // #5
    cudaEventRecord(ev_join, s_side);

    // ---- Dependent chain on main ----
    cudaStreamWaitEvent(0, ev_join, 0);
    spmm_csr_kernel<true><<<(M + 7) / 8, 256>>>(row_start, edge, H, S1, M);   // #6
    gemm_hmma_kernel<128, true><<<gemm_blocks, 256>>>(S1, W2, b2, H, M);      // #7
    spmm_csr_kernel<false><<<(M + 7) / 8, 256>>>(row_start, edge, H, out, M); // #8
}

// round 11
// speedup vs baseline: 1.4759x; 1.0710x over previous
#include <cuda_runtime.h>
#include <cuda_fp16.h>
#include <cstdint>

// ---------------------------------------------------------------------------
// GCN: out = SpMM(relu(SpMM(X@W1+b1)) @ W2 + b2)
// R11: R10 pipeline (195.1us) with ONE change: GEMM1 is now cp.async
//      double-buffered (fp32 tiles stream into smem staging, smem->smem
//      convert to the proven fp16 ldmatrix layout). Fixes the measured
//      latency stall (occ=22%, issue=13.6%, tensor=20.6%).
// ---------------------------------------------------------------------------

#define MAX_NODES 100000
#define MAX_EDGES 1600000
#define FEAT 128
#define SCAN_B 512
#define SCAN_NB ((MAX_NODES + SCAN_B - 1) / SCAN_B)

__device__ __align__(16) __half g_H [(size_t)MAX_NODES * FEAT];  // GEMM out (reused)
__device__ __align__(16) __half g_S1[(size_t)MAX_NODES * FEAT];  // relu(SpMM1)
__device__ int  g_cnt[MAX_NODES];
__device__ int  g_row_start[MAX_NODES + 1];
__device__ int  g_row_next[MAX_NODES];
__device__ int  g_partials[SCAN_NB];
__device__ int2 g_edge[MAX_EDGES];                 // {col, float_as_int(val)}

// ---------------------------------------------------------------------------
// CSR build (exact R10): hist (RED) -> scan1/2/3 (scan3 re-zeros cnt) ->
//                        scatter (atomic ticket)
// ---------------------------------------------------------------------------
__global__ void hist_kernel(const int* __restrict__ row, int nE, int* __restrict__ cnt)
{
    int i = blockIdx.x * blockDim.x + threadIdx.x;
    if (i < nE) atomicAdd(&cnt[row[i]], 1);        // returnless -> RED
}

__global__ void scan1_kernel(const int* __restrict__ cnt, int* __restrict__ partials, int n)
{
    __shared__ int sh[SCAN_B];
    int i = blockIdx.x * SCAN_B + threadIdx.x;
    sh[threadIdx.x] = (i < n) ? cnt[i] : 0;
    __syncthreads();
#pragma unroll
    for (int off = SCAN_B / 2; off > 0; off >>= 1) {
        if (threadIdx.x < off) sh[threadIdx.x] += sh[threadIdx.x + off];
        __syncthreads();
    }
    if (threadIdx.x == 0) partials[blockIdx.x] = sh[0];
}

__global__ void scan2_kernel(int* __restrict__ partials, int nb,
                             int* __restrict__ row_start, int n)
{
    __shared__ int sh[256];
    int tid = threadIdx.x;
    int v = (tid < nb) ? partials[tid] : 0;
    sh[tid] = v;
    __syncthreads();
#pragma unroll
    for (int off = 1; off < 256; off <<= 1) {
        int t = (tid >= off) ? sh[tid - off] : 0;
        __syncthreads();
        sh[tid] += t;
        __syncthreads();
    }
    if (tid < nb) partials[tid] = sh[tid] - v;
    if (tid == 255) row_start[n] = sh[255];
}

__global__ void scan3_kernel(int* __restrict__ cnt, const int* __restrict__ partials,
                             int* __restrict__ row_start, int* __restrict__ row_next, int n)
{
    __shared__ int sh[SCAN_B];
    int tid = threadIdx.x;
    int i = blockIdx.x * SCAN_B + tid;
    int v = (i < n) ? cnt[i] : 0;
    sh[tid] = v;
    __syncthreads();
#pragma unroll
    for (int off = 1; off < SCAN_B; off <<= 1) {
        int t = (tid >= off) ? sh[tid - off] : 0;
        __syncthreads();
        sh[tid] += t;
        __syncthreads();
    }
    if (i < n) {
        int excl = sh[tid] - v + partials[blockIdx.x];
        row_start[i] = excl;
        row_next[i]  = excl;
        cnt[i]       = 0;      // restore for next call
    }
}

__global__ void scatter_kernel(const int* __restrict__ row, const int* __restrict__ col,
                               const float* __restrict__ vals, int nE,
                               int* __restrict__ row_next, int2* __restrict__ edge)
{
    int i = blockIdx.x * blockDim.x + threadIdx.x;
    if (i < nE) {
        int r = row[i];
        int p = atomicAdd(&row_next[r], 1);
        edge[p] = make_int2(col[i], __float_as_int(vals[i]));
    }
}

// ---------------------------------------------------------------------------
// HMMA primitives
// ---------------------------------------------------------------------------
__device__ __forceinline__ void mma16816(float* d, const uint32_t* a, const uint32_t* b)
{
    asm volatile(
        "mma.sync.aligned.m16n8k16.row.col.f32.f16.f16.f32 "
        "{%0,%1,%2,%3}, {%4,%5,%6,%7}, {%8,%9}, {%0,%1,%2,%3};\n"
        : "+f"(d[0]), "+f"(d[1]), "+f"(d[2]), "+f"(d[3])
        : "r"(a[0]), "r"(a[1]), "r"(a[2]), "r"(a[3]), "r"(b[0]), "r"(b[1]));
}

__device__ __forceinline__ void ldsm_x4(uint32_t* r, uint32_t addr)
{
    asm volatile("ldmatrix.sync.aligned.m8n8.x4.shared.b16 {%0,%1,%2,%3}, [%4];"
                 : "=r"(r[0]), "=r"(r[1]), "=r"(r[2]), "=r"(r[3]) : "r"(addr));
}

__device__ __forceinline__ void ldsm_x4_t(uint32_t* r, uint32_t addr)
{
    asm volatile("ldmatrix.sync.aligned.m8n8.x4.trans.shared.b16 {%0,%1,%2,%3}, [%4];"
                 : "=r"(r[0]), "=r"(r[1]), "=r"(r[2]), "=r"(r[3]) : "r"(addr));
}

#define AS_STRIDE 56
#define WS_STRIDE 136

// ---------------------------------------------------------------------------
// GEMM1 (NEW): cp.async double-buffered. fp32 A/W tiles stream into smem
// staging; a smem->smem pass converts into the proven fp16 ldmatrix layout.
// Per tile: [issue cp(t+1)] wait(t)+sync -> convert(t) -> sync -> compute(t).
// Next tile's 32KB is in flight during convert+compute -> latency hidden.
// Dynamic smem layout (88576 B):
//   Af[2][128*32] f32 | Wf[2][32*128] f32 | As[128*AS_STRIDE] | Ws[32*WS_STRIDE]
// ---------------------------------------------------------------------------
__global__ __launch_bounds__(256) void gemm1_cpasync_kernel(
    const float* __restrict__ A, const float* __restrict__ W,
    const float* __restrict__ bias, __half* __restrict__ C, int M)
{
    constexpr int K = 256, BM = 128, BK = 32, N = 128;
    constexpr int T = K / BK;
    constexpr int AF_ELEMS = BM * BK;      // per buffer
    constexpr int WF_ELEMS = BK * N;

    extern __shared__ char smem_raw[];
    float*  Af = (float*)smem_raw;                                   // [2][AF]
    float*  Wf = (float*)(smem_raw + 2 * AF_ELEMS * 4);              // [2][WF]
    __half* As = (__half*)(smem_raw + 4 * AF_ELEMS * 4);             // 14336 B
    __half* Ws = (__half*)(smem_raw + 4 * AF_ELEMS * 4 + BM * AS_STRIDE * 2);

    const int tid  = threadIdx.x;
    const int lane = tid & 31;
    const int wid  = tid >> 5;
    const int wm   = wid >> 1;
    const int wn   = wid & 1;
    const int m0   = blockIdx.x * BM;

    const uint32_t sAf = (uint32_t)__cvta_generic_to_shared(Af);
    const uint32_t sWf = (uint32_t)__cvta_generic_to_shared(Wf);
    const uint32_t sAs = (uint32_t)__cvta_generic_to_shared(As);
    const uint32_t sWs = (uint32_t)__cvta_generic_to_shared(Ws);

    float acc[2][8][4];
#pragma unroll
    for (int i = 0; i < 2; i++)
#pragma unroll
        for (int j = 0; j < 8; j++)
#pragma unroll
            for (int q = 0; q < 4; q++) acc[i][j][q] = 0.f;

    auto issue_cp = [&](int t) {
        const int k0  = t * BK;
        const int buf = t & 1;
        // A tile [128 x 32] f32: 1024 16B-chunks, 4 per thread
#pragma unroll
        for (int i = 0; i < 4; i++) {
            int idx = tid + i * 256;
            int rr = idx >> 3, cc = (idx & 7) << 2;
            int gr = m0 + rr;
            int grc = (gr < M) ? gr : (M - 1);   // keep address valid
            uint32_t dst = sAf + (uint32_t)(buf * AF_ELEMS + rr * BK + cc) * 4;
            const float* src = A + (size_t)grc * K + k0 + cc;
            int sz = (gr < M) ? 16 : 0;          // zero-fill OOB rows
            asm volatile("cp.async.cg.shared.global [%0], [%1], 16, %2;"
                         :: "r"(dst), "l"(src), "r"(sz));
        }
        // W tile [32 x 128] f32: 1024 16B-chunks, 4 per thread
#pragma unroll
        for (int i = 0; i < 4; i++) {
            int idx = tid + i * 256;
            int rr = idx >> 5, cc = (idx & 31) << 2;
            uint32_t dst = sWf + (uint32_t)(buf * WF_ELEMS + rr * N + cc) * 4;
            const float* src = W + (size_t)(k0 + rr) * N + cc;
            asm volatile("cp.async.cg.shared.global [%0], [%1], 16;"
                         :: "r"(dst), "l"(src));
        }
        asm volatile("cp.async.commit_group;");
    };

    issue_cp(0);

    for (int t = 0; t < T; t++) {
        if (t + 1 < T) {
            issue_cp(t + 1);
            asm volatile("cp.async.wait_group 1;");
        } else {
            asm volatile("cp.async.wait_group 0;");
        }
        __syncthreads();                         // tile t staged for all

        // convert staged fp32 -> fp16 ldmatrix layout
        const int buf = t & 1;
#pragma unroll
        for (int i = 0; i < 4; i++) {
            int idx = tid + i * 256;
            int rr = idx >> 3, cc = (idx & 7) << 2;
            float4 v = *(const float4*)(Af + buf * AF_ELEMS + rr * BK + cc);
            __half2* dst = (__half2*)(&As[rr * AS_STRIDE + cc]);
            dst[0] = __floats2half2_rn(v.x, v.y);
            dst[1] = __floats2half2_rn(v.z, v.w);
        }
#pragma unroll
        for (int i = 0; i < 4; i++) {
            int idx = tid + i * 256;
            int rr = idx >> 5, cc = (idx & 31) << 2;
            float4 v = *(const float4*)(Wf + buf * WF_ELEMS + rr * N + cc);
            __half2* dst = (__half2*)(&Ws[rr * WS_STRIDE + cc]);
            dst[0] = __floats2half2_rn(v.x, v.y);
            dst[1] = __floats2half2_rn(v.z, v.w);
        }
        __syncthreads();                         // As/Ws ready

        // compute: 2 k16 steps (identical to proven kernel)
#pragma unroll
        for (int ks = 0; ks < 2; ks++) {
            const int kk = ks * 16;
            uint32_t a[2][4], b[4][4];
#pragma unroll
            for (int mi = 0; mi < 2; mi++) {
                int r0 = wm * 32 + mi * 16;
                uint32_t addr = sAs + ((r0 + (lane & 15)) * AS_STRIDE
                                       + kk + ((lane >> 4) << 3)) * 2;
                ldsm_x4(a[mi], addr);
            }
#pragma unroll
            for (int p = 0; p < 4; p++) {
                int c0 = wn * 64 + p * 16;
                uint32_t addr = sWs + ((kk + (lane & 15)) * WS_STRIDE
                                       + c0 + ((lane >> 4) << 3)) * 2;
                ldsm_x4_t(b[p], addr);
            }
#pragma unroll
            for (int mi = 0; mi < 2; mi++)
#pragma unroll
                for (int p = 0; p < 4; p++) {
                    mma16816(acc[mi][2 * p],     a[mi], &b[p][0]);
                    mma16816(acc[mi][2 * p + 1], a[mi], &b[p][2]);
                }
        }
        // no trailing sync: next iter's wait+sync orders convert(t+1) after
        // all compute(t); cp(t+2) writes Af only (not read by compute).
    }

    const int rq = lane >> 2;
    const int cq = (lane & 3) << 1;
#pragma unroll
    for (int ni = 0; ni < 8; ni++) {
        int gc = wn * 64 + ni * 8 + cq;
        float2 bb = *(const float2*)(bias + gc);
#pragma unroll
        for (int mi = 0; mi < 2; mi++) {
            int r_base = m0 + wm * 32 + mi * 16 + rq;
            float* d = acc[mi][ni];
            if (r_base < M)
                *(__half2*)(C + (size_t)r_base * FEAT + gc) =
                    __floats2half2_rn(d[0] + bb.x, d[1] + bb.y);
            if (r_base + 8 < M)
                *(__half2*)(C + (size_t)(r_base + 8) * FEAT + gc) =
                    __floats2half2_rn(d[2] + bb.x, d[3] + bb.y);
        }
    }
}

// ---------------------------------------------------------------------------
// GEMM2 (exact R10): fp16 A path, single-buffered.
// ---------------------------------------------------------------------------
__global__ __launch_bounds__(256) void gemm2_hmma_kernel(
    const __half* __restrict__ A, const float* __restrict__ W,
    const float* __restrict__ bias, __half* __restrict__ C, int M)
{
    constexpr int K = 128, BM = 128, BK = 32, N = 128;
    constexpr int T = K / BK;
    __shared__ __half As[BM * AS_STRIDE];
    __shared__ __half Ws[BK * WS_STRIDE];

    const int tid  = threadIdx.x;
    const int lane = tid & 31;
    const int wid  = tid >> 5;
    const int wm   = wid >> 1;
    const int wn   = wid & 1;
    const int m0   = blockIdx.x * BM;

    float acc[2][8][4];
#pragma unroll
    for (int i = 0; i < 2; i++)
#pragma unroll
        for (int j = 0; j < 8; j++)
#pragma unroll
            for (int q = 0; q < 4; q++) acc[i][j][q] = 0.f;

    const uint32_t sAs = (uint32_t)__cvta_generic_to_shared(As);
    const uint32_t sWs = (uint32_t)__cvta_generic_to_shared(Ws);

    for (int t = 0; t < T; t++) {
        const int k0 = t * BK;
#pragma unroll
        for (int i = 0; i < 2; i++) {
            int idx = tid + i * 256;
            int rr = idx >> 2, cc = (idx & 3) << 3;
            int gr = m0 + rr;
            uint4 v = make_uint4(0, 0, 0, 0);
            if (gr < M) v = *(const uint4*)(A + (size_t)gr * K + k0 + cc);
            *(uint4*)(&As[rr * AS_STRIDE + cc]) = v;
        }
#pragma unroll
        for (int i = 0; i < 4; i++) {
            int idx = tid + i * 256;
            int rr = idx >> 5, cc = (idx & 31) << 2;
            float4 v = *(const float4*)(W + (size_t)(k0 + rr) * N + cc);
            __half2* dst = (__half2*)(&Ws[rr * WS_STRIDE + cc]);
            dst[0] = __floats2half2_rn(v.x, v.y);
            dst[1] = __floats2half2_rn(v.z, v.w);
        }
        __syncthreads();

#pragma unroll
        for (int ks = 0; ks < 2; ks++) {
            const int kk = ks * 16;
            uint32_t a[2][4], b[4][4];
#pragma unroll
            for (int mi = 0; mi < 2; mi++) {
                int r0 = wm * 32 + mi * 16;
                uint32_t addr = sAs + ((r0 + (lane & 15)) * AS_STRIDE
                                       + kk + ((lane >> 4) << 3)) * 2;
                ldsm_x4(a[mi], addr);
            }
#pragma unroll
            for (int p = 0; p < 4; p++) {
                int c0 = wn * 64 + p * 16;
                uint32_t addr = sWs + ((kk + (lane & 15)) * WS_STRIDE
                                       + c0 + ((lane >> 4) << 3)) * 2;
                ldsm_x4_t(b[p], addr);
            }
#pragma unroll
            for (int mi = 0; mi < 2; mi++)
#pragma unroll
                for (int p = 0; p < 4; p++) {
                    mma16816(acc[mi][2 * p],     a[mi], &b[p][0]);
                    mma16816(acc[mi][2 * p + 1], a[mi], &b[p][2]);
                }
        }
        __syncthreads();
    }

    const int rq = lane >> 2;
    const int cq = (lane & 3) << 1;
#pragma unroll
    for (int ni = 0; ni < 8; ni++) {
        int gc = wn * 64 + ni * 8 + cq;
        float2 bb = *(const float2*)(bias + gc);
#pragma unroll
        for (int mi = 0; mi < 2; mi++) {
            int r_base = m0 + wm * 32 + mi * 16 + rq;
            float* d = acc[mi][ni];
            if (r_base < M)
                *(__half2*)(C + (size_t)r_base * N + gc) =
                    __floats2half2_rn(d[0] + bb.x, d[1] + bb.y);
            if (r_base + 8 < M)
                *(__half2*)(C + (size_t)(r_base + 8) * N + gc) =
                    __floats2half2_rn(d[2] + bb.x, d[3] + bb.y);
        }
    }
}

// ---------------------------------------------------------------------------
// CSR SpMM (exact R10): warp per row; __stcs on final fp32 store.
// ---------------------------------------------------------------------------
template <bool OUT_HALF_RELU>
__global__ __launch_bounds__(256) void spmm_csr_kernel(
    const int* __restrict__ row_start, const int2* __restrict__ edge,
    const __half* __restrict__ H, void* __restrict__ out_, int n)
{
    int r    = blockIdx.x * 8 + (threadIdx.x >> 5);
    int lane = threadIdx.x & 31;
    if (r >= n) return;

    int s = row_start[r];
    int e = row_start[r + 1];

    float4 acc = make_float4(0.f, 0.f, 0.f, 0.f);
    const int fo = lane << 2;

    auto fma_edge = [&](int2 ev) {
        float v = __int_as_float(ev.y);
        uint2 u = *(const uint2*)(H + (size_t)ev.x * FEAT + fo);
        float2 h01 = __half22float2(*(const __half2*)&u.x);
        float2 h23 = __half22float2(*(const __half2*)&u.y);
        acc.x += v * h01.x; acc.y += v * h01.y;
        acc.z += v * h23.x; acc.w += v * h23.y;
    };

    int i = s;
    for (; i + 4 <= e; i += 4) {
        int2 e0 = edge[i], e1 = edge[i + 1], e2 = edge[i + 2], e3 = edge[i + 3];
        fma_edge(e0); fma_edge(e1); fma_edge(e2); fma_edge(e3);
    }
    for (; i < e; i++) fma_edge(edge[i]);

    if (OUT_HALF_RELU) {
        __half* out = (__half*)out_;
        uint2 o;
        *(__half2*)&o.x = __floats2half2_rn(fmaxf(acc.x, 0.f), fmaxf(acc.y, 0.f));
        *(__half2*)&o.y = __floats2half2_rn(fmaxf(acc.z, 0.f), fmaxf(acc.w, 0.f));
        *(uint2*)(out + (size_t)r * FEAT + fo) = o;
    } else {
        float* out = (float*)out_;
        __stcs((float4*)(out + (size_t)r * FEAT + fo), acc);   // evict-first
    }
}

// ---------------------------------------------------------------------------
extern "C" void kernel_launch(void* const* d_in, const int* in_sizes, int n_in,
                              void* d_out, int out_size)
{
    const float* X    = (const float*)d_in[0];
    const float* W1   = (const float*)d_in[1];
    const float* b1   = (const float*)d_in[2];
    const float* W2   = (const float*)d_in[3];
    const float* b2   = (const float*)d_in[4];
    const float* vals = (const float*)d_in[5];
    const int*   row  = (const int*)d_in[6];
    const int*   col  = (const int*)d_in[7];

    const int M  = in_sizes[0] / 256;   // 100000
    const int nE = in_sizes[5];         // 1600000

    __half *H, *S1;
    int *cnt, *row_start, *row_next, *partials;
    int2 *edge;
    cudaGetSymbolAddress((void**)&H,         g_H);
    cudaGetSymbolAddress((void**)&S1,        g_S1);
    cudaGetSymbolAddress((void**)&cnt,       g_cnt);
    cudaGetSymbolAddress((void**)&row_start, g_row_start);
    cudaGetSymbolAddress((void**)&row_next,  g_row_next);
    cudaGetSymbolAddress((void**)&partials,  g_partials);
    cudaGetSymbolAddress((void**)&edge,      g_edge);
    float* out = (float*)d_out;

    // Dynamic smem for GEMM1: 2*16KB Af + 2*16KB Wf + 14336 As + 8704 Ws
    const int gemm1_smem = 2 * 128 * 32 * 4 + 2 * 32 * 128 * 4
                         + 128 * AS_STRIDE * 2 + 32 * WS_STRIDE * 2;  // 88576

    static cudaStream_t s_side = nullptr;
    static cudaEvent_t  ev_fork = nullptr, ev_join = nullptr;
    if (s_side == nullptr) {
        cudaStreamCreateWithFlags(&s_side, cudaStreamNonBlocking);
        cudaEventCreateWithFlags(&ev_fork, cudaEventDisableTiming);
        cudaEventCreateWithFlags(&ev_join, cudaEventDisableTiming);
        cudaFuncSetAttribute(gemm1_cpasync_kernel,
                             cudaFuncAttributeMaxDynamicSharedMemorySize, gemm1_smem);
    }

    const int nb = (M + SCAN_B - 1) / SCAN_B;   // 196
    const int gemm_blocks = (M + 127) / 128;

    // ---- Fork: CSR build on side stream, concurrent with GEMM1 ----
    // Enqueue order keeps GEMM1 at launch index 3 (ncu captures #3).
    cudaEventRecord(ev_fork, 0);
    cudaStreamWaitEvent(s_side, ev_fork, 0);

    hist_kernel<<<(nE + 511) / 512, 512, 0, s_side>>>(row, nE, cnt);            // #0
    scan1_kernel<<<nb, SCAN_B, 0, s_side>>>(cnt, partials, M);                  // #1
    scan2_kernel<<<1, 256, 0, s_side>>>(partials, nb, row_start, M);            // #2
    gemm1_cpasync_kernel<<<gemm_blocks, 256, gemm1_smem>>>(X, W1, b1, H, M);    // #3 (main)
    scan3_kernel<<<nb, SCAN_B, 0, s_side>>>(cnt, partials, row_start,
                                            row_next, M);                       // #4
    scatter_kernel<<<(nE + 511) / 512, 512, 0, s_side>>>(row, col, vals, nE,
                                                         row_next, edge);       // #5
    cudaEventRecord(ev_join, s_side);

    // ---- Dependent chain on main ----
    cudaStreamWaitEvent(0, ev_join, 0);
    spmm_csr_kernel<true><<<(M + 7) / 8, 256>>>(row_start, edge, H, S1, M);     // #6
    gemm2_hmma_kernel<<<gemm_blocks, 256>>>(S1, W2, b2, H, M);                  // #7
    spmm_csr_kernel<false><<<(M + 7) / 8, 256>>>(row_start, edge, H, out, M);   // #8
}

// round 12
// speedup vs baseline: 1.5406x; 1.0438x over previous
#include <cuda_runtime.h>
#include <cuda_fp16.h>
#include <cstdint>

// ---------------------------------------------------------------------------
// GCN: out = SpMM(relu(SpMM(X@W1+b1)) @ W2 + b2)
// R12: R11 (182.2us) + GEMM2 rebuilt: cp.async streams fp16 A tiles DIRECTLY
//      into the padded ldmatrix layout (no staging/convert), W2 preconverted
//      whole into smem once. Smem 63.5KB -> 3 blocks/SM.
// ---------------------------------------------------------------------------

#define MAX_NODES 100000
#define MAX_EDGES 1600000
#define FEAT 128
#define SCAN_B 512
#define SCAN_NB ((MAX_NODES + SCAN_B - 1) / SCAN_B)

__device__ __align__(16) __half g_H [(size_t)MAX_NODES * FEAT];  // GEMM out (reused)
__device__ __align__(16) __half g_S1[(size_t)MAX_NODES * FEAT];  // relu(SpMM1)
__device__ int  g_cnt[MAX_NODES];
__device__ int  g_row_start[MAX_NODES + 1];
__device__ int  g_row_next[MAX_NODES];
__device__ int  g_partials[SCAN_NB];
__device__ int2 g_edge[MAX_EDGES];                 // {col, float_as_int(val)}

// ---------------------------------------------------------------------------
// CSR build (exact R11)
// ---------------------------------------------------------------------------
__global__ void hist_kernel(const int* __restrict__ row, int nE, int* __restrict__ cnt)
{
    int i = blockIdx.x * blockDim.x + threadIdx.x;
    if (i < nE) atomicAdd(&cnt[row[i]], 1);        // returnless -> RED
}

__global__ void scan1_kernel(const int* __restrict__ cnt, int* __restrict__ partials, int n)
{
    __shared__ int sh[SCAN_B];
    int i = blockIdx.x * SCAN_B + threadIdx.x;
    sh[threadIdx.x] = (i < n) ? cnt[i] : 0;
    __syncthreads();
#pragma unroll
    for (int off = SCAN_B / 2; off > 0; off >>= 1) {
        if (threadIdx.x < off) sh[threadIdx.x] += sh[threadIdx.x + off];
        __syncthreads();
    }
    if (threadIdx.x == 0) partials[blockIdx.x] = sh[0];
}

__global__ void scan2_kernel(int* __restrict__ partials, int nb,
                             int* __restrict__ row_start, int n)
{
    __shared__ int sh[256];
    int tid = threadIdx.x;
    int v = (tid < nb) ? partials[tid] : 0;
    sh[tid] = v;
    __syncthreads();
#pragma unroll
    for (int off = 1; off < 256; off <<= 1) {
        int t = (tid >= off) ? sh[tid - off] : 0;
        __syncthreads();
        sh[tid] += t;
        __syncthreads();
    }
    if (tid < nb) partials[tid] = sh[tid] - v;
    if (tid == 255) row_start[n] = sh[255];
}

__global__ void scan3_kernel(int* __restrict__ cnt, const int* __restrict__ partials,
                             int* __restrict__ row_start, int* __restrict__ row_next, int n)
{
    __shared__ int sh[SCAN_B];
    int tid = threadIdx.x;
    int i = blockIdx.x * SCAN_B + tid;
    int v = (i < n) ? cnt[i] : 0;
    sh[tid] = v;
    __syncthreads();
#pragma unroll
    for (int off = 1; off < SCAN_B; off <<= 1) {
        int t = (tid >= off) ? sh[tid - off] : 0;
        __syncthreads();
        sh[tid] += t;
        __syncthreads();
    }
    if (i < n) {
        int excl = sh[tid] - v + partials[blockIdx.x];
        row_start[i] = excl;
        row_next[i]  = excl;
        cnt[i]       = 0;      // restore for next call
    }
}

__global__ void scatter_kernel(const int* __restrict__ row, const int* __restrict__ col,
                               const float* __restrict__ vals, int nE,
                               int* __restrict__ row_next, int2* __restrict__ edge)
{
    int i = blockIdx.x * blockDim.x + threadIdx.x;
    if (i < nE) {
        int r = row[i];
        int p = atomicAdd(&row_next[r], 1);
        edge[p] = make_int2(col[i], __float_as_int(vals[i]));
    }
}

// ---------------------------------------------------------------------------
// HMMA primitives
// ---------------------------------------------------------------------------
__device__ __forceinline__ void mma16816(float* d, const uint32_t* a, const uint32_t* b)
{
    asm volatile(
        "mma.sync.aligned.m16n8k16.row.col.f32.f16.f16.f32 "
        "{%0,%1,%2,%3}, {%4,%5,%6,%7}, {%8,%9}, {%0,%1,%2,%3};\n"
        : "+f"(d[0]), "+f"(d[1]), "+f"(d[2]), "+f"(d[3])
        : "r"(a[0]), "r"(a[1]), "r"(a[2]), "r"(a[3]), "r"(b[0]), "r"(b[1]));
}

__device__ __forceinline__ void ldsm_x4(uint32_t* r, uint32_t addr)
{
    asm volatile("ldmatrix.sync.aligned.m8n8.x4.shared.b16 {%0,%1,%2,%3}, [%4];"
                 : "=r"(r[0]), "=r"(r[1]), "=r"(r[2]), "=r"(r[3]) : "r"(addr));
}

__device__ __forceinline__ void ldsm_x4_t(uint32_t* r, uint32_t addr)
{
    asm volatile("ldmatrix.sync.aligned.m8n8.x4.trans.shared.b16 {%0,%1,%2,%3}, [%4];"
                 : "=r"(r[0]), "=r"(r[1]), "=r"(r[2]), "=r"(r[3]) : "r"(addr));
}

#define AS_STRIDE 56
#define WS_STRIDE 136

// ---------------------------------------------------------------------------
// GEMM1 (exact R11): cp.async double-buffered with fp32 staging + convert.
// ---------------------------------------------------------------------------
__global__ __launch_bounds__(256) void gemm1_cpasync_kernel(
    const float* __restrict__ A, const float* __restrict__ W,
    const float* __restrict__ bias, __half* __restrict__ C, int M)
{
    constexpr int K = 256, BM = 128, BK = 32, N = 128;
    constexpr int T = K / BK;
    constexpr int AF_ELEMS = BM * BK;
    constexpr int WF_ELEMS = BK * N;

    extern __shared__ char smem_raw[];
    float*  Af = (float*)smem_raw;
    float*  Wf = (float*)(smem_raw + 2 * AF_ELEMS * 4);
    __half* As = (__half*)(smem_raw + 4 * AF_ELEMS * 4);
    __half* Ws = (__half*)(smem_raw + 4 * AF_ELEMS * 4 + BM * AS_STRIDE * 2);

    const int tid  = threadIdx.x;
    const int lane = tid & 31;
    const int wid  = tid >> 5;
    const int wm   = wid >> 1;
    const int wn   = wid & 1;
    const int m0   = blockIdx.x * BM;

    const uint32_t sAf = (uint32_t)__cvta_generic_to_shared(Af);
    const uint32_t sWf = (uint32_t)__cvta_generic_to_shared(Wf);
    const uint32_t sAs = (uint32_t)__cvta_generic_to_shared(As);
    const uint32_t sWs = (uint32_t)__cvta_generic_to_shared(Ws);

    float acc[2][8][4];
#pragma unroll
    for (int i = 0; i < 2; i++)
#pragma unroll
        for (int j = 0; j < 8; j++)
#pragma unroll
            for (int q = 0; q < 4; q++) acc[i][j][q] = 0.f;

    auto issue_cp = [&](int t) {
        const int k0  = t * BK;
        const int buf = t & 1;
#pragma unroll
        for (int i = 0; i < 4; i++) {
            int idx = tid + i * 256;
            int rr = idx >> 3, cc = (idx & 7) << 2;
            int gr = m0 + rr;
            int grc = (gr < M) ? gr : (M - 1);
            uint32_t dst = sAf + (uint32_t)(buf * AF_ELEMS + rr * BK + cc) * 4;
            const float* src = A + (size_t)grc * K + k0 + cc;
            int sz = (gr < M) ? 16 : 0;
            asm volatile("cp.async.cg.shared.global [%0], [%1], 16, %2;"
                         :: "r"(dst), "l"(src), "r"(sz));
        }
#pragma unroll
        for (int i = 0; i < 4; i++) {
            int idx = tid + i * 256;
            int rr = idx >> 5, cc = (idx & 31) << 2;
            uint32_t dst = sWf + (uint32_t)(buf * WF_ELEMS + rr * N + cc) * 4;
            const float* src = W + (size_t)(k0 + rr) * N + cc;
            asm volatile("cp.async.cg.shared.global [%0], [%1], 16;"
                         :: "r"(dst), "l"(src));
        }
        asm volatile("cp.async.commit_group;");
    };

    issue_cp(0);

    for (int t = 0; t < T; t++) {
        if (t + 1 < T) {
            issue_cp(t + 1);
            asm volatile("cp.async.wait_group 1;");
        } else {
            asm volatile("cp.async.wait_group 0;");
        }
        __syncthreads();

        const int buf = t & 1;
#pragma unroll
        for (int i = 0; i < 4; i++) {
            int idx = tid + i * 256;
            int rr = idx >> 3, cc = (idx & 7) << 2;
            float4 v = *(const float4*)(Af + buf * AF_ELEMS + rr * BK + cc);
            __half2* dst = (__half2*)(&As[rr * AS_STRIDE + cc]);
            dst[0] = __floats2half2_rn(v.x, v.y);
            dst[1] = __floats2half2_rn(v.z, v.w);
        }
#pragma unroll
        for (int i = 0; i < 4; i++) {
            int idx = tid + i * 256;
            int rr = idx >> 5, cc = (idx & 31) << 2;
            float4 v = *(const float4*)(Wf + buf * WF_ELEMS + rr * N + cc);
            __half2* dst = (__half2*)(&Ws[rr * WS_STRIDE + cc]);
            dst[0] = __floats2half2_rn(v.x, v.y);
            dst[1] = __floats2half2_rn(v.z, v.w);
        }
        __syncthreads();

#pragma unroll
        for (int ks = 0; ks < 2; ks++) {
            const int kk = ks * 16;
            uint32_t a[2][4], b[4][4];
#pragma unroll
            for (int mi = 0; mi < 2; mi++) {
                int r0 = wm * 32 + mi * 16;
                uint32_t addr = sAs + ((r0 + (lane & 15)) * AS_STRIDE
                                       + kk + ((lane >> 4) << 3)) * 2;
                ldsm_x4(a[mi], addr);
            }
#pragma unroll
            for (int p = 0; p < 4; p++) {
                int c0 = wn * 64 + p * 16;
                uint32_t addr = sWs + ((kk + (lane & 15)) * WS_STRIDE
                                       + c0 + ((lane >> 4) << 3)) * 2;
                ldsm_x4_t(b[p], addr);
            }
#pragma unroll
            for (int mi = 0; mi < 2; mi++)
#pragma unroll
                for (int p = 0; p < 4; p++) {
                    mma16816(acc[mi][2 * p],     a[mi], &b[p][0]);
                    mma16816(acc[mi][2 * p + 1], a[mi], &b[p][2]);
                }
        }
    }

    const int rq = lane >> 2;
    const int cq = (lane & 3) << 1;
#pragma unroll
    for (int ni = 0; ni < 8; ni++) {
        int gc = wn * 64 + ni * 8 + cq;
        float2 bb = *(const float2*)(bias + gc);
#pragma unroll
        for (int mi = 0; mi < 2; mi++) {
            int r_base = m0 + wm * 32 + mi * 16 + rq;
            float* d = acc[mi][ni];
            if (r_base < M)
                *(__half2*)(C + (size_t)r_base * FEAT + gc) =
                    __floats2half2_rn(d[0] + bb.x, d[1] + bb.y);
            if (r_base + 8 < M)
                *(__half2*)(C + (size_t)(r_base + 8) * FEAT + gc) =
                    __floats2half2_rn(d[2] + bb.x, d[3] + bb.y);
        }
    }
}

// ---------------------------------------------------------------------------
// GEMM2 (NEW): fp16 A streamed by cp.async DIRECTLY into the padded ldmatrix
// layout (no staging, no convert). W2 preconverted whole into smem once.
// Per tile: issue cp(t+1) -> wait -> sync -> compute -> sync.
// Dynamic smem: As[2][128*AS_STRIDE] (28672 B) + Ws[128*WS_STRIDE] (34816 B).
// ---------------------------------------------------------------------------
__global__ __launch_bounds__(256) void gemm2_cpasync_kernel(
    const __half* __restrict__ A, const float* __restrict__ W,
    const float* __restrict__ bias, __half* __restrict__ C, int M)
{
    constexpr int K = 128, BM = 128, BK = 32, N = 128;
    constexpr int T = K / BK;                      // 4
    constexpr int AS_ELEMS = BM * AS_STRIDE;       // per buffer (halves)

    extern __shared__ char smem_raw[];
    __half* As = (__half*)smem_raw;                            // [2][AS_ELEMS]
    __half* Ws = (__half*)(smem_raw + 2 * AS_ELEMS * 2);       // [128][WS_STRIDE]

    const int tid  = threadIdx.x;
    const int lane = tid & 31;
    const int wid  = tid >> 5;
    const int wm   = wid >> 1;
    const int wn   = wid & 1;
    const int m0   = blockIdx.x * BM;

    const uint32_t sAs = (uint32_t)__cvta_generic_to_shared(As);
    const uint32_t sWs = (uint32_t)__cvta_generic_to_shared(Ws);

    float acc[2][8][4];
#pragma unroll
    for (int i = 0; i < 2; i++)
#pragma unroll
        for (int j = 0; j < 8; j++)
#pragma unroll
            for (int q = 0; q < 4; q++) acc[i][j][q] = 0.f;

    // A tile [128 x 32] fp16 = 512 16B-chunks, 2 per thread, straight into
    // the padded layout (row rr at As[rr*AS_STRIDE], cc in {0,8,16,24}).
    auto issue_cp = [&](int t) {
        const int k0  = t * BK;
        const int buf = t & 1;
#pragma unroll
        for (int i = 0; i < 2; i++) {
            int idx = tid + i * 256;
            int rr = idx >> 2, cc = (idx & 3) << 3;
            int gr = m0 + rr;
            int grc = (gr < M) ? gr : (M - 1);
            uint32_t dst = sAs + (uint32_t)(buf * AS_ELEMS + rr * AS_STRIDE + cc) * 2;
            const __half* src = A + (size_t)grc * K + k0 + cc;
            int sz = (gr < M) ? 16 : 0;
            asm volatile("cp.async.cg.shared.global [%0], [%1], 16, %2;"
                         :: "r"(dst), "l"(src), "r"(sz));
        }
        asm volatile("cp.async.commit_group;");
    };

    issue_cp(0);

    // Preconvert whole W2 (128x128 fp32 -> fp16): 16 float4 per thread.
#pragma unroll
    for (int i = 0; i < 16; i++) {
        int idx = tid + i * 256;
        int rr = idx >> 5, cc = (idx & 31) << 2;
        float4 v = *(const float4*)(W + (size_t)rr * N + cc);
        __half2* dst = (__half2*)(&Ws[rr * WS_STRIDE + cc]);
        dst[0] = __floats2half2_rn(v.x, v.y);
        dst[1] = __floats2half2_rn(v.z, v.w);
    }

    for (int t = 0; t < T; t++) {
        if (t + 1 < T) {
            issue_cp(t + 1);
            asm volatile("cp.async.wait_group 1;");
        } else {
            asm volatile("cp.async.wait_group 0;");
        }
        __syncthreads();          // tile t staged; W stores visible (t==0)

        const int buf = t & 1;
        const uint32_t sA = sAs + (uint32_t)(buf * AS_ELEMS) * 2;
#pragma unroll
        for (int ks = 0; ks < 2; ks++) {
            const int kk = ks * 16;            // within tile
            const int kg = t * BK + kk;        // within whole W
            uint32_t a[2][4], b[4][4];
#pragma unroll
            for (int mi = 0; mi < 2; mi++) {
                int r0 = wm * 32 + mi * 16;
                uint32_t addr = sA + ((r0 + (lane & 15)) * AS_STRIDE
                                      + kk + ((lane >> 4) << 3)) * 2;
                ldsm_x4(a[mi], addr);
            }
#pragma unroll
            for (int p = 0; p < 4; p++) {
                int c0 = wn * 64 + p * 16;
                uint32_t addr = sWs + ((kg + (lane & 15)) * WS_STRIDE
                                       + c0 + ((lane >> 4) << 3)) * 2;
                ldsm_x4_t(b[p], addr);
            }
#pragma unroll
            for (int mi = 0; mi < 2; mi++)
#pragma unroll
                for (int p = 0; p < 4; p++) {
                    mma16816(acc[mi][2 * p],     a[mi], &b[p][0]);
                    mma16816(acc[mi][2 * p + 1], a[mi], &b[p][2]);
                }
        }
        __syncthreads();          // compute(t) done before cp(t+2) overwrites buf
    }

    const int rq = lane >> 2;
    const int cq = (lane & 3) << 1;
#pragma unroll
    for (int ni = 0; ni < 8; ni++) {
        int gc = wn * 64 + ni * 8 + cq;
        float2 bb = *(const float2*)(bias + gc);
#pragma unroll
        for (int mi = 0; mi < 2; mi++) {
            int r_base = m0 + wm * 32 + mi * 16 + rq;
            float* d = acc[mi][ni];
            if (r_base < M)
                *(__half2*)(C + (size_t)r_base * N + gc) =
                    __floats2half2_rn(d[0] + bb.x, d[1] + bb.y);
            if (r_base + 8 < M)
                *(__half2*)(C + (size_t)(r_base + 8) * N + gc) =
                    __floats2half2_rn(d[2] + bb.x, d[3] + bb.y);
        }
    }
}

// ---------------------------------------------------------------------------
// CSR SpMM (exact R11): warp per row; __stcs on final fp32 store.
// ---------------------------------------------------------------------------
template <bool OUT_HALF_RELU>
__global__ __launch_bounds__(256) void spmm_csr_kernel(
    const int* __restrict__ row_start, const int2* __restrict__ edge,
    const __half* __restrict__ H, void* __restrict__ out_, int n)
{
    int r    = blockIdx.x * 8 + (threadIdx.x >> 5);
    int lane = threadIdx.x & 31;
    if (r >= n) return;

    int s = row_start[r];
    int e = row_start[r + 1];

    float4 acc = make_float4(0.f, 0.f, 0.f, 0.f);
    const int fo = lane << 2;

    auto fma_edge = [&](int2 ev) {
        float v = __int_as_float(ev.y);
        uint2 u = *(const uint2*)(H + (size_t)ev.x * FEAT + fo);
        float2 h01 = __half22float2(*(const __half2*)&u.x);
        float2 h23 = __half22float2(*(const __half2*)&u.y);
        acc.x += v * h01.x; acc.y += v * h01.y;
        acc.z += v * h23.x; acc.w += v * h23.y;
    };

    int i = s;
    for (; i + 4 <= e; i += 4) {
        int2 e0 = edge[i], e1 = edge[i + 1], e2 = edge[i + 2], e3 = edge[i + 3];
        fma_edge(e0); fma_edge(e1); fma_edge(e2); fma_edge(e3);
    }
    for (; i < e; i++) fma_edge(edge[i]);

    if (OUT_HALF_RELU) {
        __half* out = (__half*)out_;
        uint2 o;
        *(__half2*)&o.x = __floats2half2_rn(fmaxf(acc.x, 0.f), fmaxf(acc.y, 0.f));
        *(__half2*)&o.y = __floats2half2_rn(fmaxf(acc.z, 0.f), fmaxf(acc.w, 0.f));
        *(uint2*)(out + (size_t)r * FEAT + fo) = o;
    } else {
        float* out = (float*)out_;
        __stcs((float4*)(out + (size_t)r * FEAT + fo), acc);   // evict-first
    }
}

// ---------------------------------------------------------------------------
extern "C" void kernel_launch(void* const* d_in, const int* in_sizes, int n_in,
                              void* d_out, int out_size)
{
    const float* X    = (const float*)d_in[0];
    const float* W1   = (const float*)d_in[1];
    const float* b1   = (const float*)d_in[2];
    const float* W2   = (const float*)d_in[3];
    const float* b2   = (const float*)d_in[4];
    const float* vals = (const float*)d_in[5];
    const int*   row  = (const int*)d_in[6];
    const int*   col  = (const int*)d_in[7];

    const int M  = in_sizes[0] / 256;   // 100000
    const int nE = in_sizes[5];         // 1600000

    __half *H, *S1;
    int *cnt, *row_start, *row_next, *partials;
    int2 *edge;
    cudaGetSymbolAddress((void**)&H,         g_H);
    cudaGetSymbolAddress((void**)&S1,        g_S1);
    cudaGetSymbolAddress((void**)&cnt,       g_cnt);
    cudaGetSymbolAddress((void**)&row_start, g_row_start);
    cudaGetSymbolAddress((void**)&row_next,  g_row_next);
    cudaGetSymbolAddress((void**)&partials,  g_partials);
    cudaGetSymbolAddress((void**)&edge,      g_edge);
    float* out = (float*)d_out;

    const int gemm1_smem = 2 * 128 * 32 * 4 + 2 * 32 * 128 * 4
                         + 128 * AS_STRIDE * 2 + 32 * WS_STRIDE * 2;   // 88576
    const int gemm2_smem = 2 * 128 * AS_STRIDE * 2
                         + 128 * WS_STRIDE * 2;                        // 63488

    static cudaStream_t s_side = nullptr;
    static cudaEvent_t  ev_fork = nullptr, ev_join = nullptr;
    if (s_side == nullptr) {
        cudaStreamCreateWithFlags(&s_side, cudaStreamNonBlocking);
        cudaEventCreateWithFlags(&ev_fork, cudaEventDisableTiming);
        cudaEventCreateWithFlags(&ev_join, cudaEventDisableTiming);
        cudaFuncSetAttribute(gemm1_cpasync_kernel,
                             cudaFuncAttributeMaxDynamicSharedMemorySize, gemm1_smem);
        cudaFuncSetAttribute(gemm2_cpasync_kernel,
                             cudaFuncAttributeMaxDynamicSharedMemorySize, gemm2_smem);
    }

    const int nb = (M + SCAN_B - 1) / SCAN_B;   // 196
    const int gemm_blocks = (M + 127) / 128;

    // ---- Fork: CSR build on side stream, concurrent with GEMM1 ----
    cudaEventRecord(ev_fork, 0);
    cudaStreamWaitEvent(s_side, ev_fork, 0);

    hist_kernel<<<(nE + 511) / 512, 512, 0, s_side>>>(row, nE, cnt);            // #0
    scan1_kernel<<<nb, SCAN_B, 0, s_side>>>(cnt, partials, M);                  // #1
    scan2_kernel<<<1, 256, 0, s_side>>>(partials, nb, row_start, M);            // #2
    gemm1_cpasync_kernel<<<gemm_blocks, 256, gemm1_smem>>>(X, W1, b1, H, M);    // #3 (main)
    scan3_kernel<<<nb, SCAN_B, 0, s_side>>>(cnt, partials, row_start,
                                            row_next, M);                       // #4
    scatter_kernel<<<(nE + 511) / 512, 512, 0, s_side>>>(row, col, vals, nE,
                                                         row_next, edge);       // #5
    cudaEventRecord(ev_join, s_side);

    // ---- Dependent chain on main ----
    cudaStreamWaitEvent(0, ev_join, 0);
    spmm_csr_kernel<true><<<(M + 7) / 8, 256>>>(row_start, edge, H, S1, M);     // #6
    gemm2_cpasync_kernel<<<gemm_blocks, 256, gemm2_smem>>>(S1, W2, b2, H, M);   // #7
    spmm_csr_kernel<false><<<(M + 7) / 8, 256>>>(row_start, edge, H, out, M);   // #8
}